// round 14
// baseline (speedup 1.0000x reference)
#include <cuda_runtime.h>
#include <cuda_bf16.h>
#include <cstdint>
#include <cstring>

#define BB 2
#define S  2048
#define H  16
#define D  1024
#define DK 64
#define MROWS (BB*S)   // 4096

// ===================== warp-MMA helpers (sm_80+, valid on sm_103) =====================
#define LDSM4(r, a) asm volatile( \
    "ldmatrix.sync.aligned.m8n8.x4.shared.b16 {%0,%1,%2,%3}, [%4];" \
    : "=r"((r)[0]),"=r"((r)[1]),"=r"((r)[2]),"=r"((r)[3]) : "r"(a))
#define LDSM2(r, a) asm volatile( \
    "ldmatrix.sync.aligned.m8n8.x2.shared.b16 {%0,%1}, [%2];" \
    : "=r"((r)[0]),"=r"((r)[1]) : "r"(a))
#define LDSM2T(r, a) asm volatile( \
    "ldmatrix.sync.aligned.m8n8.x2.trans.shared.b16 {%0,%1}, [%2];" \
    : "=r"((r)[0]),"=r"((r)[1]) : "r"(a))
#define MMA16816(c, a, b) asm volatile( \
    "mma.sync.aligned.m16n8k16.row.col.f32.bf16.bf16.f32 " \
    "{%0,%1,%2,%3}, {%4,%5,%6,%7}, {%8,%9}, {%0,%1,%2,%3};" \
    : "+f"((c)[0]),"+f"((c)[1]),"+f"((c)[2]),"+f"((c)[3]) \
    : "r"((a)[0]),"r"((a)[1]),"r"((a)[2]),"r"((a)[3]), "r"((b)[0]),"r"((b)[1]))

#define CP16(dst, src) asm volatile( \
    "cp.async.cg.shared.global [%0], [%1], 16;" :: "r"(dst), "l"(src) : "memory")
#define CP_COMMIT() asm volatile("cp.async.commit_group;" ::: "memory")
#define CP_WAIT0()  asm volatile("cp.async.wait_group 0;" ::: "memory")

__device__ __forceinline__ uint32_t smem_u32(const void* p) {
    uint32_t a;
    asm("{ .reg .u64 t; cvta.to.shared.u64 t, %1; cvt.u32.u64 %0, t; }" : "=r"(a) : "l"(p));
    return a;
}

// FFMA-pipe exp; rel err ~2e-6
__device__ __forceinline__ float fexp(float x) {
    x = fmaxf(x, -87.0f);
    float y = x * 1.44269504088896341f;
    float t = y + 12582912.0f;
    int ni = __float_as_int(t) - 0x4B400000;
    float f = y - (t - 12582912.0f);
    float p = 1.33335581464284430e-3f;
    p = fmaf(p, f, 9.61812910762847716e-3f);
    p = fmaf(p, f, 5.55041086648215800e-2f);
    p = fmaf(p, f, 2.40226506959100712e-1f);
    p = fmaf(p, f, 6.93147180559945309e-1f);
    p = fmaf(p, f, 1.0f);
    return p * __int_as_float((ni + 127) << 23);
}

// ===================== device-global scratch (16B aligned) =====================
__device__ __align__(16) __nv_bfloat16 g_Xhi [3u*MROWS*D];
__device__ __align__(16) __nv_bfloat16 g_Xmid[3u*MROWS*D];
__device__ __align__(16) __nv_bfloat16 g_WhiT [4u*D*D];   // [z][n][k] transposed
__device__ __align__(16) __nv_bfloat16 g_WmidT[4u*D*D];
__device__ __align__(16) __nv_bfloat16 g_Qh[BB*H*S*DK];
__device__ __align__(16) __nv_bfloat16 g_Qm[BB*H*S*DK];
__device__ __align__(16) __nv_bfloat16 g_Kh[BB*H*S*DK];
__device__ __align__(16) __nv_bfloat16 g_Km[BB*H*S*DK];
__device__ __align__(16) __nv_bfloat16 g_Vh[BB*H*S*DK];
__device__ __align__(16) __nv_bfloat16 g_Vm[BB*H*S*DK];
__device__ __align__(16) __nv_bfloat16 g_ctx_hi [MROWS*D];
__device__ __align__(16) __nv_bfloat16 g_ctx_mid[MROWS*D];
__device__ __align__(16) float g_rinv[BB*H*S];

// ===================== prep: split activations =====================
__global__ __launch_bounds__(256) void conv_acts(
    const float* __restrict__ q, const float* __restrict__ k, const float* __restrict__ v)
{
    const size_t per4 = (size_t)MROWS * D / 4;
    size_t i = (size_t)blockIdx.x * 256 + threadIdx.x;
    int z = (int)(i / per4);
    size_t r = i - (size_t)z * per4;
    const float* src = (z == 0) ? q : (z == 1) ? k : v;
    float4 x = ((const float4*)src)[r];
    __nv_bfloat16 h0 = __float2bfloat16(x.x), h1 = __float2bfloat16(x.y);
    __nv_bfloat16 h2 = __float2bfloat16(x.z), h3 = __float2bfloat16(x.w);
    size_t o = i * 4;
    ((__nv_bfloat162*)(g_Xhi + o))[0] = __halves2bfloat162(h0, h1);
    ((__nv_bfloat162*)(g_Xhi + o))[1] = __halves2bfloat162(h2, h3);
    ((__nv_bfloat162*)(g_Xmid + o))[0] = __halves2bfloat162(
        __float2bfloat16(x.x - __bfloat162float(h0)), __float2bfloat16(x.y - __bfloat162float(h1)));
    ((__nv_bfloat162*)(g_Xmid + o))[1] = __halves2bfloat162(
        __float2bfloat16(x.z - __bfloat162float(h2)), __float2bfloat16(x.w - __bfloat162float(h3)));
}

// ===================== prep: split + transpose weights =====================
__global__ __launch_bounds__(256) void conv_W(
    const float* __restrict__ Wq, const float* __restrict__ Wk,
    const float* __restrict__ Wv, const float* __restrict__ Wo)
{
    __shared__ __nv_bfloat16 th[64][68];
    __shared__ __nv_bfloat16 tm[64][68];
    const int z = blockIdx.z;
    const float* src = (z == 0) ? Wq : (z == 1) ? Wk : (z == 2) ? Wv : Wo;
    const int k0 = blockIdx.y * 64, n0 = blockIdx.x * 64;
    const int t = threadIdx.x;
    #pragma unroll
    for (int p = 0; p < 4; p++) {
        int r = p * 16 + (t >> 4);
        int c4 = (t & 15) * 4;
        float4 w = *(const float4*)&src[(size_t)(k0 + r) * D + n0 + c4];
        float vv[4] = {w.x, w.y, w.z, w.w};
        #pragma unroll
        for (int j = 0; j < 4; j++) {
            __nv_bfloat16 hh = __float2bfloat16(vv[j]);
            th[c4 + j][r] = hh;
            tm[c4 + j][r] = __float2bfloat16(vv[j] - __bfloat162float(hh));
        }
    }
    __syncthreads();
    #pragma unroll
    for (int p = 0; p < 4; p++) {
        int n = p * 16 + (t >> 4);
        int k4 = (t & 15) * 4;
        size_t o = (size_t)z * D * D + (size_t)(n0 + n) * D + k0 + k4;
        *(uint2*)&g_WhiT[o]  = *(const uint2*)&th[n][k4];
        *(uint2*)&g_WmidT[o] = *(const uint2*)&tm[n][k4];
    }
}

// ===================== HMMA GEMM mainloop (128x128 CTA tile, K=1024) =====================
#define LDA 144
#define TILE_B (128*LDA)     // 18432
#define OFF_AM TILE_B
#define OFF_BH (2*TILE_B)
#define OFF_BM (3*TILE_B)
#define GEMM_SMEM (4*TILE_B) // 73728

__device__ __forceinline__ void hgemm_main(
    const __nv_bfloat16* __restrict__ Ah, const __nv_bfloat16* __restrict__ Am,
    const __nv_bfloat16* __restrict__ Bh, const __nv_bfloat16* __restrict__ Bm,
    char* smem, float acc[4][4][4])
{
    const int tid = threadIdx.x, lane = tid & 31, wid = tid >> 5;
    const int wm = wid >> 2, wn = wid & 3;
    const uint32_t sb = smem_u32(smem);

    const uint32_t a_row = (uint32_t)(wm * 64 + (lane & 15)) * LDA + (lane >> 4) * 16;
    const uint32_t b_row = (uint32_t)(wn * 32 + (lane & 7)) * LDA + ((lane >> 3) & 1) * 16;

    for (int ch = 0; ch < 16; ch++) {
        const int kb = ch * 64;
        #pragma unroll
        for (int p = 0; p < 8; p++) {
            int idx = p * 256 + tid;
            int row = idx >> 4, cg = idx & 15;
            size_t g = (size_t)row * D + kb + cg * 4;
            int so = row * LDA + cg * 8;
            *(uint2*)(smem + so)          = *(const uint2*)(Ah + g);
            *(uint2*)(smem + OFF_AM + so) = *(const uint2*)(Am + g);
            *(uint2*)(smem + OFF_BH + so) = *(const uint2*)(Bh + g);
            *(uint2*)(smem + OFF_BM + so) = *(const uint2*)(Bm + g);
        }
        __syncthreads();

        #pragma unroll
        for (int ks = 0; ks < 4; ks++) {
            uint32_t ah[4][4], am[4][4], bh[4][2], bm[4][2];
            #pragma unroll
            for (int mt = 0; mt < 4; mt++) {
                uint32_t ra = sb + a_row + mt * (16 * LDA) + ks * 32;
                LDSM4(ah[mt], ra);
                LDSM4(am[mt], ra + OFF_AM);
            }
            #pragma unroll
            for (int nt = 0; nt < 4; nt++) {
                uint32_t rb = sb + OFF_BH + b_row + nt * (8 * LDA) + ks * 32;
                LDSM2(bh[nt], rb);
                LDSM2(bm[nt], rb + (OFF_BM - OFF_BH));
            }
            #pragma unroll
            for (int mt = 0; mt < 4; mt++)
                #pragma unroll
                for (int nt = 0; nt < 4; nt++) {
                    MMA16816(acc[mt][nt], ah[mt], bh[nt]);
                    MMA16816(acc[mt][nt], ah[mt], bm[nt]);
                    MMA16816(acc[mt][nt], am[mt], bh[nt]);
                }
        }
        __syncthreads();
    }
}

// ===================== QKV GEMM: epilogue writes split bf16 head-major =====================
__global__ __launch_bounds__(256) void qkv_mm(
    const float* __restrict__ bq, const float* __restrict__ bk, const float* __restrict__ bv)
{
    extern __shared__ char smem[];
    const int z = blockIdx.z, m0 = blockIdx.y * 128, n0 = blockIdx.x * 128;
    float acc[4][4][4] = {};
    hgemm_main(g_Xhi + ((size_t)z * MROWS + m0) * D, g_Xmid + ((size_t)z * MROWS + m0) * D,
               g_WhiT + ((size_t)z * D + n0) * D,    g_WmidT + ((size_t)z * D + n0) * D,
               smem, acc);

    const float* bias = (z == 0) ? bq : (z == 1) ? bk : bv;
    __nv_bfloat16* outh = (z == 0) ? g_Qh : (z == 1) ? g_Kh : g_Vh;
    __nv_bfloat16* outm = (z == 0) ? g_Qm : (z == 1) ? g_Km : g_Vm;
    const int tid = threadIdx.x, lane = tid & 31, wid = tid >> 5;
    const int wm = wid >> 2, wn = wid & 3;
    const int g2 = lane >> 2, t4 = lane & 3;

    #pragma unroll
    for (int nt = 0; nt < 4; nt++) {
        const int c = n0 + wn * 32 + nt * 8 + 2 * t4;
        const float b0v = __ldg(&bias[c]), b1v = __ldg(&bias[c + 1]);
        const int h = c >> 6, d = c & 63;
        #pragma unroll
        for (int mt = 0; mt < 4; mt++) {
            int r0 = m0 + wm * 64 + mt * 16 + g2;
            int b = r0 >> 11, s = r0 & (S - 1);
            size_t base = ((size_t)(b * H + h) * S + s) * DK + d;
            #pragma unroll
            for (int hp = 0; hp < 2; hp++) {
                float v0 = acc[mt][nt][2*hp + 0] + b0v;
                float v1 = acc[mt][nt][2*hp + 1] + b1v;
                __nv_bfloat16 h0 = __float2bfloat16(v0), h1 = __float2bfloat16(v1);
                size_t o = base + (size_t)hp * 8 * DK;
                *(__nv_bfloat162*)(outh + o) = __halves2bfloat162(h0, h1);
                *(__nv_bfloat162*)(outm + o) = __halves2bfloat162(
                    __float2bfloat16(v0 - __bfloat162float(h0)),
                    __float2bfloat16(v1 - __bfloat162float(h1)));
            }
        }
    }
}

// ===================== O-proj GEMM (row-major epilogue) =====================
__global__ __launch_bounds__(256) void o_mm(const float* __restrict__ bo, float* __restrict__ out)
{
    extern __shared__ char smem[];
    const int m0 = blockIdx.y * 128, n0 = blockIdx.x * 128;
    float acc[4][4][4] = {};
    hgemm_main(g_ctx_hi + (size_t)m0 * D, g_ctx_mid + (size_t)m0 * D,
               g_WhiT + ((size_t)3 * D + n0) * D, g_WmidT + ((size_t)3 * D + n0) * D,
               smem, acc);

    const int tid = threadIdx.x, lane = tid & 31, wid = tid >> 5;
    const int wm = wid >> 2, wn = wid & 3;
    const int g2 = lane >> 2, t4 = lane & 3;

    #pragma unroll
    for (int nt = 0; nt < 4; nt++) {
        const int c = n0 + wn * 32 + nt * 8 + 2 * t4;
        const float b0v = __ldg(&bo[c]), b1v = __ldg(&bo[c + 1]);
        #pragma unroll
        for (int mt = 0; mt < 4; mt++) {
            int r0 = m0 + wm * 64 + mt * 16 + g2;
            float* p0 = out + (size_t)r0 * D + c;
            *(float2*)p0 = make_float2(acc[mt][nt][0] + b0v, acc[mt][nt][1] + b1v);
            float* p1 = p0 + 8 * D;
            *(float2*)p1 = make_float2(acc[mt][nt][2] + b0v, acc[mt][nt][3] + b1v);
        }
    }
}

// ===================== attention kernel 1: row sums, 64-row q-tiles (round-12 best) =====
#define ST_QH 0
#define ST_QM 9216
#define ST_K0 18432
#define ST_K1 36864
#define ST_SMEM 55296

__global__ __launch_bounds__(256) void stats_mm()
{
    extern __shared__ char smem[];
    const uint32_t sb = smem_u32(smem);
    const int tid = threadIdx.x, lane = tid & 31, wid = tid >> 5;
    const int wm = wid >> 2, wn = wid & 3;
    const int g2 = lane >> 2, t4 = lane & 3;
    const int q0 = blockIdx.x * 64, bh = blockIdx.y;

    const __nv_bfloat16* Qh = g_Qh + ((size_t)bh * S + q0) * DK;
    const __nv_bfloat16* Qm = g_Qm + ((size_t)bh * S + q0) * DK;
    const __nv_bfloat16* Kh = g_Kh + (size_t)bh * S * DK;
    const __nv_bfloat16* Km = g_Km + (size_t)bh * S * DK;

    #pragma unroll
    for (int p = 0; p < 4; p++) {
        int idx = p * 256 + tid;
        int row = idx >> 4, cg = idx & 15;
        size_t g = (size_t)row * DK + cg * 4;
        int so = row * LDA + cg * 8;
        *(uint2*)(smem + ST_QH + so) = *(const uint2*)(Qh + g);
        *(uint2*)(smem + ST_QM + so) = *(const uint2*)(Qm + g);
    }

    #pragma unroll
    for (int p = 0; p < 2; p++) {
        int idx = p * 256 + tid;
        int row = idx >> 3, cg = idx & 7;
        uint32_t so = sb + ST_K0 + row * LDA + cg * 16;
        CP16(so,        (const char*)(Kh + (size_t)row * DK) + cg * 16);
        CP16(so + 9216, (const char*)(Km + (size_t)row * DK) + cg * 16);
    }
    CP_COMMIT();

    const uint32_t aQ = sb + ST_QH + (uint32_t)(wm * 32 + (lane & 15)) * LDA + (lane >> 4) * 16;
    const uint32_t bKoff = (uint32_t)(wn * 16 + (lane & 7)) * LDA + ((lane >> 3) & 1) * 16;

    float sums[2][2] = {};

    for (int c = 0; c < 32; c++) {
        CP_WAIT0();
        __syncthreads();
        if (c + 1 < 32) {
            const int kt = (c + 1) * 64;
            const uint32_t kb = sb + (((c + 1) & 1) ? ST_K1 : ST_K0);
            #pragma unroll
            for (int p = 0; p < 2; p++) {
                int idx = p * 256 + tid;
                int row = idx >> 3, cg = idx & 7;
                uint32_t so = kb + row * LDA + cg * 16;
                CP16(so,        (const char*)(Kh + (size_t)(kt + row) * DK) + cg * 16);
                CP16(so + 9216, (const char*)(Km + (size_t)(kt + row) * DK) + cg * 16);
            }
            CP_COMMIT();
        }

        const uint32_t bK = sb + ((c & 1) ? ST_K1 : ST_K0) + bKoff;
        float sacc[2][2][4] = {};
        #pragma unroll
        for (int ks = 0; ks < 4; ks++) {
            uint32_t qh[2][4], qm[2][4];
            #pragma unroll
            for (int mt = 0; mt < 2; mt++) {
                uint32_t ra = aQ + mt * (16 * LDA) + ks * 32;
                LDSM4(qh[mt], ra);
                LDSM4(qm[mt], ra + (ST_QM - ST_QH));
            }
            #pragma unroll
            for (int nt = 0; nt < 2; nt++) {
                uint32_t rb = bK + nt * (8 * LDA) + ks * 32;
                uint32_t kbh[2], kbm[2];
                LDSM2(kbh, rb);
                LDSM2(kbm, rb + 9216);
                #pragma unroll
                for (int mt = 0; mt < 2; mt++) {
                    MMA16816(sacc[mt][nt], qh[mt], kbh);
                    MMA16816(sacc[mt][nt], qh[mt], kbm);
                    MMA16816(sacc[mt][nt], qm[mt], kbh);
                }
            }
        }
        #pragma unroll
        for (int mt = 0; mt < 2; mt++)
            #pragma unroll
            for (int nt = 0; nt < 2; nt++) {
                sums[mt][0] += fexp(sacc[mt][nt][0] * 0.125f) + fexp(sacc[mt][nt][1] * 0.125f);
                sums[mt][1] += fexp(sacc[mt][nt][2] * 0.125f) + fexp(sacc[mt][nt][3] * 0.125f);
            }
    }

    #pragma unroll
    for (int mt = 0; mt < 2; mt++)
        #pragma unroll
        for (int hp = 0; hp < 2; hp++) {
            sums[mt][hp] += __shfl_xor_sync(0xffffffffu, sums[mt][hp], 1);
            sums[mt][hp] += __shfl_xor_sync(0xffffffffu, sums[mt][hp], 2);
        }
    __syncthreads();
    float* sbuf = (float*)(smem + ST_K0);
    if (t4 == 0) {
        #pragma unroll
        for (int mt = 0; mt < 2; mt++)
            #pragma unroll
            for (int hp = 0; hp < 2; hp++)
                sbuf[wn * 64 + wm * 32 + mt * 16 + g2 + 8 * hp] = sums[mt][hp];
    }
    __syncthreads();
    if (tid < 64) {
        float s = sbuf[tid] + sbuf[64 + tid] + sbuf[128 + tid] + sbuf[192 + tid];
        g_rinv[(size_t)bh * S + q0 + tid] = 1.0f / s;
    }
}

// ===================== attention kernel 2: fused softmax-apply + k-split PV ============
// grid (16 m-tiles, 32 bh), block 256. Warp layout 4x2 (rows x key-halves).
// P is warp-private (each warp PVs its own 32 k-cols over all 64 d-cols);
// partial O reduced across wn pairs at the end.
// smem: QH@0, QM@18432, KH@36864, KM@46080, VH@55296, VM@64512,
//       PH@73728, PM@92160, RINV@110592 -> 111104
#define FB_QH   0
#define FB_QM   18432
#define FB_KH   36864
#define FB_KM   46080
#define FB_VH   55296
#define FB_VM   64512
#define FB_PH   73728
#define FB_PM   92160
#define FB_RINV 110592
#define FB_SMEM 111104

__global__ __launch_bounds__(256, 2) void fused_pv(float* __restrict__ attn)
{
    extern __shared__ char smem[];
    const uint32_t sb = smem_u32(smem);
    float* sRinv = (float*)(smem + FB_RINV);

    const int tid = threadIdx.x, lane = tid & 31, wid = tid >> 5;
    const int wm = wid >> 1, wn = wid & 1;
    const int g2 = lane >> 2, t4 = lane & 3;
    const int q0 = blockIdx.x * 128, bh = blockIdx.y;
    const int b = bh >> 4, h = bh & 15;

    const __nv_bfloat16* Qh = g_Qh + ((size_t)bh * S + q0) * DK;
    const __nv_bfloat16* Qm = g_Qm + ((size_t)bh * S + q0) * DK;
    const __nv_bfloat16* Kh = g_Kh + (size_t)bh * S * DK;
    const __nv_bfloat16* Km = g_Km + (size_t)bh * S * DK;
    const __nv_bfloat16* Vh = g_Vh + (size_t)bh * S * DK;
    const __nv_bfloat16* Vm = g_Vm + (size_t)bh * S * DK;
    float* attnBase = attn + ((size_t)bh * S + q0) * S;

    #pragma unroll
    for (int p = 0; p < 8; p++) {
        int idx = p * 256 + tid;
        int row = idx >> 4, cg = idx & 15;
        size_t g = (size_t)row * DK + cg * 4;
        int so = row * LDA + cg * 8;
        *(uint2*)(smem + FB_QH + so) = *(const uint2*)(Qh + g);
        *(uint2*)(smem + FB_QM + so) = *(const uint2*)(Qm + g);
    }
    if (tid < 128) sRinv[tid] = g_rinv[(size_t)bh * S + q0 + tid];

    const uint32_t aQ = sb + FB_QH + (uint32_t)(wm * 32 + (lane & 15)) * LDA + (lane >> 4) * 16;
    const uint32_t bK = sb + FB_KH + (uint32_t)(wn * 32 + (lane & 7)) * LDA + ((lane >> 3) & 1) * 16;
    // P A-frag: warp-private block rows [wm*32,+32), k-cols [wn*32,+32)
    const uint32_t aP = sb + FB_PH + (uint32_t)(wm * 32 + (lane & 15)) * LDA +
                        (lane >> 4) * 16 + wn * 64;
    // V B-frag: rows restricted to warp's k-range [wn*32,+32), all 64 d-cols
    const uint32_t bV = sb + FB_VH +
        (uint32_t)(wn * 32 + (lane & 7) + ((lane >> 3) & 1) * 8) * LDA;

    float pacc[2][8][4] = {};

    for (int kt = 0; kt < S; kt += 64) {
        // load K + V chunks (both splits)
        #pragma unroll
        for (int p = 0; p < 4; p++) {
            int idx = p * 256 + tid;
            int row = idx >> 4, cg = idx & 15;
            size_t g = (size_t)(kt + row) * DK + cg * 4;
            int so = row * LDA + cg * 8;
            *(uint2*)(smem + FB_KH + so) = *(const uint2*)(Kh + g);
            *(uint2*)(smem + FB_KM + so) = *(const uint2*)(Km + g);
            *(uint2*)(smem + FB_VH + so) = *(const uint2*)(Vh + g);
            *(uint2*)(smem + FB_VM + so) = *(const uint2*)(Vm + g);
        }
        __syncthreads();

        // scores (warp: 32 rows x 32 k-cols)
        float sacc[2][4][4] = {};
        #pragma unroll
        for (int ks = 0; ks < 4; ks++) {
            uint32_t qh[2][4], qm[2][4], kbh[4][2], kbm[4][2];
            #pragma unroll
            for (int mt = 0; mt < 2; mt++) {
                uint32_t ra = aQ + mt * (16 * LDA) + ks * 32;
                LDSM4(qh[mt], ra);
                LDSM4(qm[mt], ra + (FB_QM - FB_QH));
            }
            #pragma unroll
            for (int nt = 0; nt < 4; nt++) {
                uint32_t rb = bK + nt * (8 * LDA) + ks * 32;
                LDSM2(kbh[nt], rb);
                LDSM2(kbm[nt], rb + (FB_KM - FB_KH));
                #pragma unroll
                for (int mt = 0; mt < 2; mt++) {
                    MMA16816(sacc[mt][nt], qh[mt], kbh[nt]);
                    MMA16816(sacc[mt][nt], qh[mt], kbm[nt]);
                    MMA16816(sacc[mt][nt], qm[mt], kbh[nt]);
                }
            }
        }

        // softmax-apply (fixed max = 0): write attn + split-bf16 P (warp-private block)
        #pragma unroll
        for (int mt = 0; mt < 2; mt++) {
            int rl0 = wm * 32 + mt * 16 + g2;
            float iv0 = sRinv[rl0], iv1 = sRinv[rl0 + 8];
            #pragma unroll
            for (int nt = 0; nt < 4; nt++) {
                int cl = wn * 32 + nt * 8 + t4 * 2;
                float p00 = fexp(sacc[mt][nt][0] * 0.125f) * iv0;
                float p01 = fexp(sacc[mt][nt][1] * 0.125f) * iv0;
                float p10 = fexp(sacc[mt][nt][2] * 0.125f) * iv1;
                float p11 = fexp(sacc[mt][nt][3] * 0.125f) * iv1;
                *(float2*)(attnBase + (size_t)rl0 * S + kt + cl)       = make_float2(p00, p01);
                *(float2*)(attnBase + (size_t)(rl0 + 8) * S + kt + cl) = make_float2(p10, p11);
                __nv_bfloat16 h00 = __float2bfloat16(p00), h01 = __float2bfloat16(p01);
                __nv_bfloat16 h10 = __float2bfloat16(p10), h11 = __float2bfloat16(p11);
                *(__nv_bfloat162*)(smem + FB_PH + rl0 * LDA + cl * 2) = __halves2bfloat162(h00, h01);
                *(__nv_bfloat162*)(smem + FB_PH + (rl0 + 8) * LDA + cl * 2) = __halves2bfloat162(h10, h11);
                *(__nv_bfloat162*)(smem + FB_PM + rl0 * LDA + cl * 2) = __halves2bfloat162(
                    __float2bfloat16(p00 - __bfloat162float(h00)),
                    __float2bfloat16(p01 - __bfloat162float(h01)));
                *(__nv_bfloat162*)(smem + FB_PM + (rl0 + 8) * LDA + cl * 2) = __halves2bfloat162(
                    __float2bfloat16(p10 - __bfloat162float(h10)),
                    __float2bfloat16(p11 - __bfloat162float(h11)));
            }
        }
        __syncwarp();   // P block is warp-private: warp-level visibility suffices

        // k-split PV: warp's 32 k-cols x all 64 d-cols
        #pragma unroll
        for (int ks = 0; ks < 2; ks++) {
            uint32_t ph[2][4], pm[2][4];
            #pragma unroll
            for (int mt = 0; mt < 2; mt++) {
                uint32_t ra = aP + mt * (16 * LDA) + ks * 32;
                LDSM4(ph[mt], ra);
                LDSM4(pm[mt], ra + (FB_PM - FB_PH));
            }
            #pragma unroll
            for (int nt = 0; nt < 8; nt++) {
                uint32_t rv = bV + ks * (16 * LDA) + nt * 16;
                uint32_t vh2[2], vm2[2];
                LDSM2T(vh2, rv);
                LDSM2T(vm2, rv + (FB_VM - FB_VH));
                #pragma unroll
                for (int mt = 0; mt < 2; mt++) {
                    MMA16816(pacc[mt][nt], ph[mt], vh2);
                    MMA16816(pacc[mt][nt], ph[mt], vm2);
                    MMA16816(pacc[mt][nt], pm[mt], vh2);
                }
            }
        }
        __syncthreads();   // V consumed before next chunk overwrite
    }

    // cross-warp reduction over wn pairs (reuse P area: 32KB)
    float* red = (float*)(smem + FB_PH);
    if (wn == 1) {
        #pragma unroll
        for (int mt = 0; mt < 2; mt++)
            #pragma unroll
            for (int nt = 0; nt < 8; nt++)
                *(float4*)&red[(((wm * 2 + mt) * 8) + nt) * 128 + lane * 4] =
                    *(float4*)pacc[mt][nt];
    }
    __syncthreads();
    if (wn == 0) {
        #pragma unroll
        for (int mt = 0; mt < 2; mt++) {
            int r0 = q0 + wm * 32 + mt * 16 + g2;
            #pragma unroll
            for (int nt = 0; nt < 8; nt++) {
                float4 o = *(float4*)&red[(((wm * 2 + mt) * 8) + nt) * 128 + lane * 4];
                float v0 = pacc[mt][nt][0] + o.x, v1 = pacc[mt][nt][1] + o.y;
                float v2 = pacc[mt][nt][2] + o.z, v3 = pacc[mt][nt][3] + o.w;
                const int c = h * DK + nt * 8 + 2 * t4;
                __nv_bfloat16 h0 = __float2bfloat16(v0), h1 = __float2bfloat16(v1);
                size_t oo = ((size_t)(b * S) + r0) * D + c;
                *(__nv_bfloat162*)(g_ctx_hi + oo) = __halves2bfloat162(h0, h1);
                *(__nv_bfloat162*)(g_ctx_mid + oo) = __halves2bfloat162(
                    __float2bfloat16(v0 - __bfloat162float(h0)),
                    __float2bfloat16(v1 - __bfloat162float(h1)));
                __nv_bfloat16 h2 = __float2bfloat16(v2), h3 = __float2bfloat16(v3);
                size_t o1 = ((size_t)(b * S) + r0 + 8) * D + c;
                *(__nv_bfloat162*)(g_ctx_hi + o1) = __halves2bfloat162(h2, h3);
                *(__nv_bfloat162*)(g_ctx_mid + o1) = __halves2bfloat162(
                    __float2bfloat16(v2 - __bfloat162float(h2)),
                    __float2bfloat16(v3 - __bfloat162float(h3)));
            }
        }
    }
}

// ===================== launch =====================
extern "C" void kernel_launch(void* const* d_in, const int* in_sizes, int n_in,
                              void* d_out, int out_size)
{
    const float* query = (const float*)d_in[0];
    const float* key   = (const float*)d_in[1];
    const float* value = (const float*)d_in[2];
    const float* Wq = (const float*)d_in[3];
    const float* bq = (const float*)d_in[4];
    const float* Wk = (const float*)d_in[5];
    const float* bk = (const float*)d_in[6];
    const float* Wv = (const float*)d_in[7];
    const float* bv = (const float*)d_in[8];
    const float* Wo = (const float*)d_in[9];
    const float* bo = (const float*)d_in[10];

    float* out  = (float*)d_out;
    float* attn = out + (size_t)MROWS * D;

    cudaFuncSetAttribute(qkv_mm, cudaFuncAttributeMaxDynamicSharedMemorySize, GEMM_SMEM);
    cudaFuncSetAttribute(o_mm, cudaFuncAttributeMaxDynamicSharedMemorySize, GEMM_SMEM);
    cudaFuncSetAttribute(stats_mm, cudaFuncAttributeMaxDynamicSharedMemorySize, ST_SMEM);
    cudaFuncSetAttribute(fused_pv, cudaFuncAttributeMaxDynamicSharedMemorySize, FB_SMEM);

    conv_acts<<<3 * MROWS * D / 4 / 256, 256>>>(query, key, value);
    conv_W<<<dim3(16, 16, 4), 256>>>(Wq, Wk, Wv, Wo);
    qkv_mm<<<dim3(8, 32, 3), 256, GEMM_SMEM>>>(bq, bk, bv);
    stats_mm<<<dim3(32, 32), 256, ST_SMEM>>>();
    fused_pv<<<dim3(16, 32), 256, FB_SMEM>>>(attn);
    o_mm<<<dim3(8, 32), 256, GEMM_SMEM>>>(bo, out);
}

// round 15
// speedup vs baseline: 1.1886x; 1.1886x over previous
#include <cuda_runtime.h>
#include <cuda_bf16.h>
#include <cstdint>
#include <cstring>

#define BB 2
#define S  2048
#define H  16
#define D  1024
#define DK 64
#define MROWS (BB*S)   // 4096

// ===================== warp-MMA helpers (sm_80+, valid on sm_103) =====================
#define LDSM4(r, a) asm volatile( \
    "ldmatrix.sync.aligned.m8n8.x4.shared.b16 {%0,%1,%2,%3}, [%4];" \
    : "=r"((r)[0]),"=r"((r)[1]),"=r"((r)[2]),"=r"((r)[3]) : "r"(a))
#define LDSM2(r, a) asm volatile( \
    "ldmatrix.sync.aligned.m8n8.x2.shared.b16 {%0,%1}, [%2];" \
    : "=r"((r)[0]),"=r"((r)[1]) : "r"(a))
#define LDSM2T(r, a) asm volatile( \
    "ldmatrix.sync.aligned.m8n8.x2.trans.shared.b16 {%0,%1}, [%2];" \
    : "=r"((r)[0]),"=r"((r)[1]) : "r"(a))
#define MMA16816(c, a, b) asm volatile( \
    "mma.sync.aligned.m16n8k16.row.col.f32.bf16.bf16.f32 " \
    "{%0,%1,%2,%3}, {%4,%5,%6,%7}, {%8,%9}, {%0,%1,%2,%3};" \
    : "+f"((c)[0]),"+f"((c)[1]),"+f"((c)[2]),"+f"((c)[3]) \
    : "r"((a)[0]),"r"((a)[1]),"r"((a)[2]),"r"((a)[3]), "r"((b)[0]),"r"((b)[1]))

#define CP16(dst, src) asm volatile( \
    "cp.async.cg.shared.global [%0], [%1], 16;" :: "r"(dst), "l"(src) : "memory")
#define CP_COMMIT() asm volatile("cp.async.commit_group;" ::: "memory")
#define CP_WAIT0()  asm volatile("cp.async.wait_group 0;" ::: "memory")

__device__ __forceinline__ uint32_t smem_u32(const void* p) {
    uint32_t a;
    asm("{ .reg .u64 t; cvta.to.shared.u64 t, %1; cvt.u32.u64 %0, t; }" : "=r"(a) : "l"(p));
    return a;
}

// FFMA-pipe exp; rel err ~2e-6
__device__ __forceinline__ float fexp(float x) {
    x = fmaxf(x, -87.0f);
    float y = x * 1.44269504088896341f;
    float t = y + 12582912.0f;
    int ni = __float_as_int(t) - 0x4B400000;
    float f = y - (t - 12582912.0f);
    float p = 1.33335581464284430e-3f;
    p = fmaf(p, f, 9.61812910762847716e-3f);
    p = fmaf(p, f, 5.55041086648215800e-2f);
    p = fmaf(p, f, 2.40226506959100712e-1f);
    p = fmaf(p, f, 6.93147180559945309e-1f);
    p = fmaf(p, f, 1.0f);
    return p * __int_as_float((ni + 127) << 23);
}

// ===================== device-global scratch (16B aligned) =====================
__device__ __align__(16) __nv_bfloat16 g_Xhi [3u*MROWS*D];
__device__ __align__(16) __nv_bfloat16 g_Xmid[3u*MROWS*D];
__device__ __align__(16) __nv_bfloat16 g_WhiT [4u*D*D];   // [z][n][k] transposed
__device__ __align__(16) __nv_bfloat16 g_WmidT[4u*D*D];
__device__ __align__(16) __nv_bfloat16 g_Qh[BB*H*S*DK];
__device__ __align__(16) __nv_bfloat16 g_Qm[BB*H*S*DK];
__device__ __align__(16) __nv_bfloat16 g_Kh[BB*H*S*DK];
__device__ __align__(16) __nv_bfloat16 g_Km[BB*H*S*DK];
__device__ __align__(16) __nv_bfloat16 g_Vh[BB*H*S*DK];
__device__ __align__(16) __nv_bfloat16 g_Vm[BB*H*S*DK];
__device__ __align__(16) __nv_bfloat16 g_ctx_hi [MROWS*D];
__device__ __align__(16) __nv_bfloat16 g_ctx_mid[MROWS*D];
__device__ __align__(16) float g_rinv[BB*H*S];

// ===================== prep: split activations =====================
__global__ __launch_bounds__(256) void conv_acts(
    const float* __restrict__ q, const float* __restrict__ k, const float* __restrict__ v)
{
    const size_t per4 = (size_t)MROWS * D / 4;
    size_t i = (size_t)blockIdx.x * 256 + threadIdx.x;
    int z = (int)(i / per4);
    size_t r = i - (size_t)z * per4;
    const float* src = (z == 0) ? q : (z == 1) ? k : v;
    float4 x = ((const float4*)src)[r];
    __nv_bfloat16 h0 = __float2bfloat16(x.x), h1 = __float2bfloat16(x.y);
    __nv_bfloat16 h2 = __float2bfloat16(x.z), h3 = __float2bfloat16(x.w);
    size_t o = i * 4;
    ((__nv_bfloat162*)(g_Xhi + o))[0] = __halves2bfloat162(h0, h1);
    ((__nv_bfloat162*)(g_Xhi + o))[1] = __halves2bfloat162(h2, h3);
    ((__nv_bfloat162*)(g_Xmid + o))[0] = __halves2bfloat162(
        __float2bfloat16(x.x - __bfloat162float(h0)), __float2bfloat16(x.y - __bfloat162float(h1)));
    ((__nv_bfloat162*)(g_Xmid + o))[1] = __halves2bfloat162(
        __float2bfloat16(x.z - __bfloat162float(h2)), __float2bfloat16(x.w - __bfloat162float(h3)));
}

// ===================== prep: split + transpose weights =====================
__global__ __launch_bounds__(256) void conv_W(
    const float* __restrict__ Wq, const float* __restrict__ Wk,
    const float* __restrict__ Wv, const float* __restrict__ Wo)
{
    __shared__ __nv_bfloat16 th[64][68];
    __shared__ __nv_bfloat16 tm[64][68];
    const int z = blockIdx.z;
    const float* src = (z == 0) ? Wq : (z == 1) ? Wk : (z == 2) ? Wv : Wo;
    const int k0 = blockIdx.y * 64, n0 = blockIdx.x * 64;
    const int t = threadIdx.x;
    #pragma unroll
    for (int p = 0; p < 4; p++) {
        int r = p * 16 + (t >> 4);
        int c4 = (t & 15) * 4;
        float4 w = *(const float4*)&src[(size_t)(k0 + r) * D + n0 + c4];
        float vv[4] = {w.x, w.y, w.z, w.w};
        #pragma unroll
        for (int j = 0; j < 4; j++) {
            __nv_bfloat16 hh = __float2bfloat16(vv[j]);
            th[c4 + j][r] = hh;
            tm[c4 + j][r] = __float2bfloat16(vv[j] - __bfloat162float(hh));
        }
    }
    __syncthreads();
    #pragma unroll
    for (int p = 0; p < 4; p++) {
        int n = p * 16 + (t >> 4);
        int k4 = (t & 15) * 4;
        size_t o = (size_t)z * D * D + (size_t)(n0 + n) * D + k0 + k4;
        *(uint2*)&g_WhiT[o]  = *(const uint2*)&th[n][k4];
        *(uint2*)&g_WmidT[o] = *(const uint2*)&tm[n][k4];
    }
}

// ===================== HMMA GEMM mainloop: cp.async pipelined, 32-k stages =============
// Stage: 4 sub-tiles (Ah, Am, Bh, Bm), each 128 rows x 64 B (32 bf16), row stride 80 B.
// 80 % 128 = 80 -> 8-row ldmatrix groups hit distinct 16B banks (conflict-free).
#define PLDA 80
#define PTILE (128*PLDA)       // 10240
#define STG   (4*PTILE)        // 40960
#define GEMM_SMEM (2*STG)      // 81920

#define HG_PREFETCH(sidx, buf) do { \
    _Pragma("unroll") \
    for (int p = 0; p < 2; p++) { \
        int idx = p * 256 + tid; \
        int row = idx >> 2, cg = idx & 3; \
        uint32_t so = (buf) + row * PLDA + cg * 16; \
        size_t gofs = (size_t)row * D + (sidx) * 32; \
        CP16(so,             (const char*)(Ah + gofs) + cg * 16); \
        CP16(so +   PTILE,   (const char*)(Am + gofs) + cg * 16); \
        CP16(so + 2*PTILE,   (const char*)(Bh + gofs) + cg * 16); \
        CP16(so + 3*PTILE,   (const char*)(Bm + gofs) + cg * 16); \
    } \
    CP_COMMIT(); \
} while (0)

__device__ __forceinline__ void hgemm_main(
    const __nv_bfloat16* __restrict__ Ah, const __nv_bfloat16* __restrict__ Am,
    const __nv_bfloat16* __restrict__ Bh, const __nv_bfloat16* __restrict__ Bm,
    char* smem, float acc[4][4][4])
{
    const int tid = threadIdx.x, lane = tid & 31, wid = tid >> 5;
    const int wm = wid >> 2, wn = wid & 3;
    const uint32_t sb = smem_u32(smem);

    HG_PREFETCH(0, sb);

    const uint32_t a_row = (uint32_t)(wm * 64 + (lane & 15)) * PLDA + (lane >> 4) * 16;
    const uint32_t b_row = (uint32_t)(wn * 32 + (lane & 7)) * PLDA + ((lane >> 3) & 1) * 16;

    for (int s = 0; s < 32; s++) {
        CP_WAIT0();
        __syncthreads();
        if (s + 1 < 32) HG_PREFETCH(s + 1, sb + (uint32_t)(((s + 1) & 1) * STG));

        const uint32_t base = sb + (uint32_t)((s & 1) * STG);
        #pragma unroll
        for (int ks = 0; ks < 2; ks++) {
            uint32_t ah[4][4], am[4][4], bh[4][2], bm[4][2];
            #pragma unroll
            for (int mt = 0; mt < 4; mt++) {
                uint32_t ra = base + a_row + mt * (16 * PLDA) + ks * 32;
                LDSM4(ah[mt], ra);
                LDSM4(am[mt], ra + PTILE);
            }
            #pragma unroll
            for (int nt = 0; nt < 4; nt++) {
                uint32_t rb = base + 2 * PTILE + b_row + nt * (8 * PLDA) + ks * 32;
                LDSM2(bh[nt], rb);
                LDSM2(bm[nt], rb + PTILE);
            }
            #pragma unroll
            for (int mt = 0; mt < 4; mt++)
                #pragma unroll
                for (int nt = 0; nt < 4; nt++) {
                    MMA16816(acc[mt][nt], ah[mt], bh[nt]);
                    MMA16816(acc[mt][nt], ah[mt], bm[nt]);
                    MMA16816(acc[mt][nt], am[mt], bh[nt]);
                }
        }
    }
    __syncthreads();
}

// ===================== QKV GEMM: epilogue writes split bf16 head-major =====================
__global__ __launch_bounds__(256) void qkv_mm(
    const float* __restrict__ bq, const float* __restrict__ bk, const float* __restrict__ bv)
{
    extern __shared__ char smem[];
    const int z = blockIdx.z, m0 = blockIdx.y * 128, n0 = blockIdx.x * 128;
    float acc[4][4][4] = {};
    hgemm_main(g_Xhi + ((size_t)z * MROWS + m0) * D, g_Xmid + ((size_t)z * MROWS + m0) * D,
               g_WhiT + ((size_t)z * D + n0) * D,    g_WmidT + ((size_t)z * D + n0) * D,
               smem, acc);

    const float* bias = (z == 0) ? bq : (z == 1) ? bk : bv;
    __nv_bfloat16* outh = (z == 0) ? g_Qh : (z == 1) ? g_Kh : g_Vh;
    __nv_bfloat16* outm = (z == 0) ? g_Qm : (z == 1) ? g_Km : g_Vm;
    const int tid = threadIdx.x, lane = tid & 31, wid = tid >> 5;
    const int wm = wid >> 2, wn = wid & 3;
    const int g2 = lane >> 2, t4 = lane & 3;

    #pragma unroll
    for (int nt = 0; nt < 4; nt++) {
        const int c = n0 + wn * 32 + nt * 8 + 2 * t4;
        const float b0v = __ldg(&bias[c]), b1v = __ldg(&bias[c + 1]);
        const int h = c >> 6, d = c & 63;
        #pragma unroll
        for (int mt = 0; mt < 4; mt++) {
            int r0 = m0 + wm * 64 + mt * 16 + g2;
            int b = r0 >> 11, s = r0 & (S - 1);
            size_t base = ((size_t)(b * H + h) * S + s) * DK + d;
            #pragma unroll
            for (int hp = 0; hp < 2; hp++) {
                float v0 = acc[mt][nt][2*hp + 0] + b0v;
                float v1 = acc[mt][nt][2*hp + 1] + b1v;
                __nv_bfloat16 h0 = __float2bfloat16(v0), h1 = __float2bfloat16(v1);
                size_t o = base + (size_t)hp * 8 * DK;
                *(__nv_bfloat162*)(outh + o) = __halves2bfloat162(h0, h1);
                *(__nv_bfloat162*)(outm + o) = __halves2bfloat162(
                    __float2bfloat16(v0 - __bfloat162float(h0)),
                    __float2bfloat16(v1 - __bfloat162float(h1)));
            }
        }
    }
}

// ===================== O-proj GEMM (row-major epilogue) =====================
__global__ __launch_bounds__(256) void o_mm(const float* __restrict__ bo, float* __restrict__ out)
{
    extern __shared__ char smem[];
    const int m0 = blockIdx.y * 128, n0 = blockIdx.x * 128;
    float acc[4][4][4] = {};
    hgemm_main(g_ctx_hi + (size_t)m0 * D, g_ctx_mid + (size_t)m0 * D,
               g_WhiT + ((size_t)3 * D + n0) * D, g_WmidT + ((size_t)3 * D + n0) * D,
               smem, acc);

    const int tid = threadIdx.x, lane = tid & 31, wid = tid >> 5;
    const int wm = wid >> 2, wn = wid & 3;
    const int g2 = lane >> 2, t4 = lane & 3;

    #pragma unroll
    for (int nt = 0; nt < 4; nt++) {
        const int c = n0 + wn * 32 + nt * 8 + 2 * t4;
        const float b0v = __ldg(&bo[c]), b1v = __ldg(&bo[c + 1]);
        #pragma unroll
        for (int mt = 0; mt < 4; mt++) {
            int r0 = m0 + wm * 64 + mt * 16 + g2;
            float* p0 = out + (size_t)r0 * D + c;
            *(float2*)p0 = make_float2(acc[mt][nt][0] + b0v, acc[mt][nt][1] + b1v);
            float* p1 = p0 + 8 * D;
            *(float2*)p1 = make_float2(acc[mt][nt][2] + b0v, acc[mt][nt][3] + b1v);
        }
    }
}

// ===================== attention kernel 1: row sums, 64-row q-tiles (measured best) =====
#define LDA 144
#define ST_QH 0
#define ST_QM 9216
#define ST_K0 18432
#define ST_K1 36864
#define ST_SMEM 55296

__global__ __launch_bounds__(256) void stats_mm()
{
    extern __shared__ char smem[];
    const uint32_t sb = smem_u32(smem);
    const int tid = threadIdx.x, lane = tid & 31, wid = tid >> 5;
    const int wm = wid >> 2, wn = wid & 3;
    const int g2 = lane >> 2, t4 = lane & 3;
    const int q0 = blockIdx.x * 64, bh = blockIdx.y;

    const __nv_bfloat16* Qh = g_Qh + ((size_t)bh * S + q0) * DK;
    const __nv_bfloat16* Qm = g_Qm + ((size_t)bh * S + q0) * DK;
    const __nv_bfloat16* Kh = g_Kh + (size_t)bh * S * DK;
    const __nv_bfloat16* Km = g_Km + (size_t)bh * S * DK;

    #pragma unroll
    for (int p = 0; p < 4; p++) {
        int idx = p * 256 + tid;
        int row = idx >> 4, cg = idx & 15;
        size_t g = (size_t)row * DK + cg * 4;
        int so = row * LDA + cg * 8;
        *(uint2*)(smem + ST_QH + so) = *(const uint2*)(Qh + g);
        *(uint2*)(smem + ST_QM + so) = *(const uint2*)(Qm + g);
    }

    #pragma unroll
    for (int p = 0; p < 2; p++) {
        int idx = p * 256 + tid;
        int row = idx >> 3, cg = idx & 7;
        uint32_t so = sb + ST_K0 + row * LDA + cg * 16;
        CP16(so,        (const char*)(Kh + (size_t)row * DK) + cg * 16);
        CP16(so + 9216, (const char*)(Km + (size_t)row * DK) + cg * 16);
    }
    CP_COMMIT();

    const uint32_t aQ = sb + ST_QH + (uint32_t)(wm * 32 + (lane & 15)) * LDA + (lane >> 4) * 16;
    const uint32_t bKoff = (uint32_t)(wn * 16 + (lane & 7)) * LDA + ((lane >> 3) & 1) * 16;

    float sums[2][2] = {};

    for (int c = 0; c < 32; c++) {
        CP_WAIT0();
        __syncthreads();
        if (c + 1 < 32) {
            const int kt = (c + 1) * 64;
            const uint32_t kb = sb + (((c + 1) & 1) ? ST_K1 : ST_K0);
            #pragma unroll
            for (int p = 0; p < 2; p++) {
                int idx = p * 256 + tid;
                int row = idx >> 3, cg = idx & 7;
                uint32_t so = kb + row * LDA + cg * 16;
                CP16(so,        (const char*)(Kh + (size_t)(kt + row) * DK) + cg * 16);
                CP16(so + 9216, (const char*)(Km + (size_t)(kt + row) * DK) + cg * 16);
            }
            CP_COMMIT();
        }

        const uint32_t bK = sb + ((c & 1) ? ST_K1 : ST_K0) + bKoff;
        float sacc[2][2][4] = {};
        #pragma unroll
        for (int ks = 0; ks < 4; ks++) {
            uint32_t qh[2][4], qm[2][4];
            #pragma unroll
            for (int mt = 0; mt < 2; mt++) {
                uint32_t ra = aQ + mt * (16 * LDA) + ks * 32;
                LDSM4(qh[mt], ra);
                LDSM4(qm[mt], ra + (ST_QM - ST_QH));
            }
            #pragma unroll
            for (int nt = 0; nt < 2; nt++) {
                uint32_t rb = bK + nt * (8 * LDA) + ks * 32;
                uint32_t kbh[2], kbm[2];
                LDSM2(kbh, rb);
                LDSM2(kbm, rb + 9216);
                #pragma unroll
                for (int mt = 0; mt < 2; mt++) {
                    MMA16816(sacc[mt][nt], qh[mt], kbh);
                    MMA16816(sacc[mt][nt], qh[mt], kbm);
                    MMA16816(sacc[mt][nt], qm[mt], kbh);
                }
            }
        }
        #pragma unroll
        for (int mt = 0; mt < 2; mt++)
            #pragma unroll
            for (int nt = 0; nt < 2; nt++) {
                sums[mt][0] += fexp(sacc[mt][nt][0] * 0.125f) + fexp(sacc[mt][nt][1] * 0.125f);
                sums[mt][1] += fexp(sacc[mt][nt][2] * 0.125f) + fexp(sacc[mt][nt][3] * 0.125f);
            }
    }

    #pragma unroll
    for (int mt = 0; mt < 2; mt++)
        #pragma unroll
        for (int hp = 0; hp < 2; hp++) {
            sums[mt][hp] += __shfl_xor_sync(0xffffffffu, sums[mt][hp], 1);
            sums[mt][hp] += __shfl_xor_sync(0xffffffffu, sums[mt][hp], 2);
        }
    __syncthreads();
    float* sbuf = (float*)(smem + ST_K0);
    if (t4 == 0) {
        #pragma unroll
        for (int mt = 0; mt < 2; mt++)
            #pragma unroll
            for (int hp = 0; hp < 2; hp++)
                sbuf[wn * 64 + wm * 32 + mt * 16 + g2 + 8 * hp] = sums[mt][hp];
    }
    __syncthreads();
    if (tid < 64) {
        float s = sbuf[tid] + sbuf[64 + tid] + sbuf[128 + tid] + sbuf[192 + tid];
        g_rinv[(size_t)bh * S + q0 + tid] = 1.0f / s;
    }
}

// ===================== attention kernel 2: fused softmax-apply + PV (round-13 best) =====
#define FB_QH   0
#define FB_QM   18432
#define FB_KH   36864
#define FB_KM   46080
#define FB_VH   55296
#define FB_VM   64512
#define FB_PH   73728
#define FB_PM   92160
#define FB_RINV 110592
#define FB_SMEM 111104

__global__ __launch_bounds__(256) void fused_pv(float* __restrict__ attn)
{
    extern __shared__ char smem[];
    const uint32_t sb = smem_u32(smem);
    float* sRinv = (float*)(smem + FB_RINV);

    const int tid = threadIdx.x, lane = tid & 31, wid = tid >> 5;
    const int wm = wid >> 1, wn = wid & 1;
    const int g2 = lane >> 2, t4 = lane & 3;
    const int q0 = blockIdx.x * 128, bh = blockIdx.y;
    const int b = bh >> 4, h = bh & 15;

    const __nv_bfloat16* Qh = g_Qh + ((size_t)bh * S + q0) * DK;
    const __nv_bfloat16* Qm = g_Qm + ((size_t)bh * S + q0) * DK;
    const __nv_bfloat16* Kh = g_Kh + (size_t)bh * S * DK;
    const __nv_bfloat16* Km = g_Km + (size_t)bh * S * DK;
    const __nv_bfloat16* Vh = g_Vh + (size_t)bh * S * DK;
    const __nv_bfloat16* Vm = g_Vm + (size_t)bh * S * DK;
    float* attnBase = attn + ((size_t)bh * S + q0) * S;

    #pragma unroll
    for (int p = 0; p < 8; p++) {
        int idx = p * 256 + tid;
        int row = idx >> 4, cg = idx & 15;
        size_t g = (size_t)row * DK + cg * 4;
        int so = row * LDA + cg * 8;
        *(uint2*)(smem + FB_QH + so) = *(const uint2*)(Qh + g);
        *(uint2*)(smem + FB_QM + so) = *(const uint2*)(Qm + g);
    }
    if (tid < 128) sRinv[tid] = g_rinv[(size_t)bh * S + q0 + tid];

    const uint32_t aQ = sb + FB_QH + (uint32_t)(wm * 32 + (lane & 15)) * LDA + (lane >> 4) * 16;
    const uint32_t bK = sb + FB_KH + (uint32_t)(wn * 32 + (lane & 7)) * LDA + ((lane >> 3) & 1) * 16;
    const uint32_t aP = sb + FB_PH + (uint32_t)(wm * 32 + (lane & 15)) * LDA + (lane >> 4) * 16;
    const uint32_t bV = sb + FB_VH +
        (uint32_t)((lane & 7) + ((lane >> 3) & 1) * 8) * LDA + wn * 64;

    float pacc[2][4][4] = {};

    for (int kt = 0; kt < S; kt += 64) {
        #pragma unroll
        for (int p = 0; p < 4; p++) {
            int idx = p * 256 + tid;
            int row = idx >> 4, cg = idx & 15;
            size_t g = (size_t)(kt + row) * DK + cg * 4;
            int so = row * LDA + cg * 8;
            *(uint2*)(smem + FB_KH + so) = *(const uint2*)(Kh + g);
            *(uint2*)(smem + FB_KM + so) = *(const uint2*)(Km + g);
            *(uint2*)(smem + FB_VH + so) = *(const uint2*)(Vh + g);
            *(uint2*)(smem + FB_VM + so) = *(const uint2*)(Vm + g);
        }
        __syncthreads();

        float sacc[2][4][4] = {};
        #pragma unroll
        for (int ks = 0; ks < 4; ks++) {
            uint32_t qh[2][4], qm[2][4], kbh[4][2], kbm[4][2];
            #pragma unroll
            for (int mt = 0; mt < 2; mt++) {
                uint32_t ra = aQ + mt * (16 * LDA) + ks * 32;
                LDSM4(qh[mt], ra);
                LDSM4(qm[mt], ra + (FB_QM - FB_QH));
            }
            #pragma unroll
            for (int nt = 0; nt < 4; nt++) {
                uint32_t rb = bK + nt * (8 * LDA) + ks * 32;
                LDSM2(kbh[nt], rb);
                LDSM2(kbm[nt], rb + (FB_KM - FB_KH));
                #pragma unroll
                for (int mt = 0; mt < 2; mt++) {
                    MMA16816(sacc[mt][nt], qh[mt], kbh[nt]);
                    MMA16816(sacc[mt][nt], qh[mt], kbm[nt]);
                    MMA16816(sacc[mt][nt], qm[mt], kbh[nt]);
                }
            }
        }

        #pragma unroll
        for (int mt = 0; mt < 2; mt++) {
            int rl0 = wm * 32 + mt * 16 + g2;
            float iv0 = sRinv[rl0], iv1 = sRinv[rl0 + 8];
            #pragma unroll
            for (int nt = 0; nt < 4; nt++) {
                int cl = wn * 32 + nt * 8 + t4 * 2;
                float p00 = fexp(sacc[mt][nt][0] * 0.125f) * iv0;
                float p01 = fexp(sacc[mt][nt][1] * 0.125f) * iv0;
                float p10 = fexp(sacc[mt][nt][2] * 0.125f) * iv1;
                float p11 = fexp(sacc[mt][nt][3] * 0.125f) * iv1;
                *(float2*)(attnBase + (size_t)rl0 * S + kt + cl)       = make_float2(p00, p01);
                *(float2*)(attnBase + (size_t)(rl0 + 8) * S + kt + cl) = make_float2(p10, p11);
                __nv_bfloat16 h00 = __float2bfloat16(p00), h01 = __float2bfloat16(p01);
                __nv_bfloat16 h10 = __float2bfloat16(p10), h11 = __float2bfloat16(p11);
                *(__nv_bfloat162*)(smem + FB_PH + rl0 * LDA + cl * 2) = __halves2bfloat162(h00, h01);
                *(__nv_bfloat162*)(smem + FB_PH + (rl0 + 8) * LDA + cl * 2) = __halves2bfloat162(h10, h11);
                *(__nv_bfloat162*)(smem + FB_PM + rl0 * LDA + cl * 2) = __halves2bfloat162(
                    __float2bfloat16(p00 - __bfloat162float(h00)),
                    __float2bfloat16(p01 - __bfloat162float(h01)));
                *(__nv_bfloat162*)(smem + FB_PM + (rl0 + 8) * LDA + cl * 2) = __halves2bfloat162(
                    __float2bfloat16(p10 - __bfloat162float(h10)),
                    __float2bfloat16(p11 - __bfloat162float(h11)));
            }
        }
        __syncthreads();

        #pragma unroll
        for (int ks = 0; ks < 4; ks++) {
            uint32_t ph[2][4], pm[2][4];
            #pragma unroll
            for (int mt = 0; mt < 2; mt++) {
                uint32_t ra = aP + mt * (16 * LDA) + ks * 32;
                LDSM4(ph[mt], ra);
                LDSM4(pm[mt], ra + (FB_PM - FB_PH));
            }
            #pragma unroll
            for (int nt = 0; nt < 4; nt++) {
                uint32_t rv = bV + ks * (16 * LDA) + nt * 16;
                uint32_t vh2[2], vm2[2];
                LDSM2T(vh2, rv);
                LDSM2T(vm2, rv + (FB_VM - FB_VH));
                #pragma unroll
                for (int mt = 0; mt < 2; mt++) {
                    MMA16816(pacc[mt][nt], ph[mt], vh2);
                    MMA16816(pacc[mt][nt], ph[mt], vm2);
                    MMA16816(pacc[mt][nt], pm[mt], vh2);
                }
            }
        }
        __syncthreads();
    }

    #pragma unroll
    for (int nt = 0; nt < 4; nt++) {
        const int c = h * DK + wn * 32 + nt * 8 + 2 * t4;
        #pragma unroll
        for (int mt = 0; mt < 2; mt++) {
            int r0 = q0 + wm * 32 + mt * 16 + g2;
            #pragma unroll
            for (int hp = 0; hp < 2; hp++) {
                float v0 = pacc[mt][nt][2*hp + 0], v1 = pacc[mt][nt][2*hp + 1];
                __nv_bfloat16 h0 = __float2bfloat16(v0), h1 = __float2bfloat16(v1);
                size_t o = ((size_t)(b * S) + r0 + 8 * hp) * D + c;
                *(__nv_bfloat162*)(g_ctx_hi + o) = __halves2bfloat162(h0, h1);
                *(__nv_bfloat162*)(g_ctx_mid + o) = __halves2bfloat162(
                    __float2bfloat16(v0 - __bfloat162float(h0)),
                    __float2bfloat16(v1 - __bfloat162float(h1)));
            }
        }
    }
}

// ===================== launch =====================
extern "C" void kernel_launch(void* const* d_in, const int* in_sizes, int n_in,
                              void* d_out, int out_size)
{
    const float* query = (const float*)d_in[0];
    const float* key   = (const float*)d_in[1];
    const float* value = (const float*)d_in[2];
    const float* Wq = (const float*)d_in[3];
    const float* bq = (const float*)d_in[4];
    const float* Wk = (const float*)d_in[5];
    const float* bk = (const float*)d_in[6];
    const float* Wv = (const float*)d_in[7];
    const float* bv = (const float*)d_in[8];
    const float* Wo = (const float*)d_in[9];
    const float* bo = (const float*)d_in[10];

    float* out  = (float*)d_out;
    float* attn = out + (size_t)MROWS * D;

    cudaFuncSetAttribute(qkv_mm, cudaFuncAttributeMaxDynamicSharedMemorySize, GEMM_SMEM);
    cudaFuncSetAttribute(o_mm, cudaFuncAttributeMaxDynamicSharedMemorySize, GEMM_SMEM);
    cudaFuncSetAttribute(stats_mm, cudaFuncAttributeMaxDynamicSharedMemorySize, ST_SMEM);
    cudaFuncSetAttribute(fused_pv, cudaFuncAttributeMaxDynamicSharedMemorySize, FB_SMEM);

    conv_acts<<<3 * MROWS * D / 4 / 256, 256>>>(query, key, value);
    conv_W<<<dim3(16, 16, 4), 256>>>(Wq, Wk, Wv, Wo);
    qkv_mm<<<dim3(8, 32, 3), 256, GEMM_SMEM>>>(bq, bk, bv);
    stats_mm<<<dim3(32, 32), 256, ST_SMEM>>>();
    fused_pv<<<dim3(16, 32), 256, FB_SMEM>>>(attn);
    o_mm<<<dim3(8, 32), 256, GEMM_SMEM>>>(bo, out);
}

// round 16
// speedup vs baseline: 1.2008x; 1.0103x over previous
#include <cuda_runtime.h>
#include <cuda_bf16.h>
#include <cstdint>
#include <cstring>

#define BB 2
#define S  2048
#define H  16
#define D  1024
#define DK 64
#define MROWS (BB*S)   // 4096

// ===================== warp-MMA helpers (sm_80+, valid on sm_103) =====================
#define LDSM4(r, a) asm volatile( \
    "ldmatrix.sync.aligned.m8n8.x4.shared.b16 {%0,%1,%2,%3}, [%4];" \
    : "=r"((r)[0]),"=r"((r)[1]),"=r"((r)[2]),"=r"((r)[3]) : "r"(a))
#define LDSM2(r, a) asm volatile( \
    "ldmatrix.sync.aligned.m8n8.x2.shared.b16 {%0,%1}, [%2];" \
    : "=r"((r)[0]),"=r"((r)[1]) : "r"(a))
#define LDSM2T(r, a) asm volatile( \
    "ldmatrix.sync.aligned.m8n8.x2.trans.shared.b16 {%0,%1}, [%2];" \
    : "=r"((r)[0]),"=r"((r)[1]) : "r"(a))
#define MMA16816(c, a, b) asm volatile( \
    "mma.sync.aligned.m16n8k16.row.col.f32.bf16.bf16.f32 " \
    "{%0,%1,%2,%3}, {%4,%5,%6,%7}, {%8,%9}, {%0,%1,%2,%3};" \
    : "+f"((c)[0]),"+f"((c)[1]),"+f"((c)[2]),"+f"((c)[3]) \
    : "r"((a)[0]),"r"((a)[1]),"r"((a)[2]),"r"((a)[3]), "r"((b)[0]),"r"((b)[1]))

#define CP16(dst, src) asm volatile( \
    "cp.async.cg.shared.global [%0], [%1], 16;" :: "r"(dst), "l"(src) : "memory")
#define CP_COMMIT() asm volatile("cp.async.commit_group;" ::: "memory")
#define CP_WAIT0()  asm volatile("cp.async.wait_group 0;" ::: "memory")

__device__ __forceinline__ uint32_t smem_u32(const void* p) {
    uint32_t a;
    asm("{ .reg .u64 t; cvta.to.shared.u64 t, %1; cvt.u32.u64 %0, t; }" : "=r"(a) : "l"(p));
    return a;
}

// FFMA-pipe exp; rel err ~2e-6
__device__ __forceinline__ float fexp(float x) {
    x = fmaxf(x, -87.0f);
    float y = x * 1.44269504088896341f;
    float t = y + 12582912.0f;
    int ni = __float_as_int(t) - 0x4B400000;
    float f = y - (t - 12582912.0f);
    float p = 1.33335581464284430e-3f;
    p = fmaf(p, f, 9.61812910762847716e-3f);
    p = fmaf(p, f, 5.55041086648215800e-2f);
    p = fmaf(p, f, 2.40226506959100712e-1f);
    p = fmaf(p, f, 6.93147180559945309e-1f);
    p = fmaf(p, f, 1.0f);
    return p * __int_as_float((ni + 127) << 23);
}

// ===================== device-global scratch (16B aligned) =====================
__device__ __align__(16) __nv_bfloat16 g_Xhi [3u*MROWS*D];
__device__ __align__(16) __nv_bfloat16 g_Xmid[3u*MROWS*D];
__device__ __align__(16) __nv_bfloat16 g_WhiT [4u*D*D];   // [z][n][k] transposed
__device__ __align__(16) __nv_bfloat16 g_WmidT[4u*D*D];
__device__ __align__(16) __nv_bfloat16 g_Qh[BB*H*S*DK];
__device__ __align__(16) __nv_bfloat16 g_Qm[BB*H*S*DK];
__device__ __align__(16) __nv_bfloat16 g_Kh[BB*H*S*DK];
__device__ __align__(16) __nv_bfloat16 g_Km[BB*H*S*DK];
__device__ __align__(16) __nv_bfloat16 g_Vh[BB*H*S*DK];
__device__ __align__(16) __nv_bfloat16 g_Vm[BB*H*S*DK];
__device__ __align__(16) __nv_bfloat16 g_ctx_hi [MROWS*D];
__device__ __align__(16) __nv_bfloat16 g_ctx_mid[MROWS*D];
__device__ __align__(16) float g_rinv[BB*H*S];

// ===================== prep: split activations =====================
__global__ __launch_bounds__(256) void conv_acts(
    const float* __restrict__ q, const float* __restrict__ k, const float* __restrict__ v)
{
    const size_t per4 = (size_t)MROWS * D / 4;
    size_t i = (size_t)blockIdx.x * 256 + threadIdx.x;
    int z = (int)(i / per4);
    size_t r = i - (size_t)z * per4;
    const float* src = (z == 0) ? q : (z == 1) ? k : v;
    float4 x = ((const float4*)src)[r];
    __nv_bfloat16 h0 = __float2bfloat16(x.x), h1 = __float2bfloat16(x.y);
    __nv_bfloat16 h2 = __float2bfloat16(x.z), h3 = __float2bfloat16(x.w);
    size_t o = i * 4;
    ((__nv_bfloat162*)(g_Xhi + o))[0] = __halves2bfloat162(h0, h1);
    ((__nv_bfloat162*)(g_Xhi + o))[1] = __halves2bfloat162(h2, h3);
    ((__nv_bfloat162*)(g_Xmid + o))[0] = __halves2bfloat162(
        __float2bfloat16(x.x - __bfloat162float(h0)), __float2bfloat16(x.y - __bfloat162float(h1)));
    ((__nv_bfloat162*)(g_Xmid + o))[1] = __halves2bfloat162(
        __float2bfloat16(x.z - __bfloat162float(h2)), __float2bfloat16(x.w - __bfloat162float(h3)));
}

// ===================== prep: split + transpose weights =====================
__global__ __launch_bounds__(256) void conv_W(
    const float* __restrict__ Wq, const float* __restrict__ Wk,
    const float* __restrict__ Wv, const float* __restrict__ Wo)
{
    __shared__ __nv_bfloat16 th[64][68];
    __shared__ __nv_bfloat16 tm[64][68];
    const int z = blockIdx.z;
    const float* src = (z == 0) ? Wq : (z == 1) ? Wk : (z == 2) ? Wv : Wo;
    const int k0 = blockIdx.y * 64, n0 = blockIdx.x * 64;
    const int t = threadIdx.x;
    #pragma unroll
    for (int p = 0; p < 4; p++) {
        int r = p * 16 + (t >> 4);
        int c4 = (t & 15) * 4;
        float4 w = *(const float4*)&src[(size_t)(k0 + r) * D + n0 + c4];
        float vv[4] = {w.x, w.y, w.z, w.w};
        #pragma unroll
        for (int j = 0; j < 4; j++) {
            __nv_bfloat16 hh = __float2bfloat16(vv[j]);
            th[c4 + j][r] = hh;
            tm[c4 + j][r] = __float2bfloat16(vv[j] - __bfloat162float(hh));
        }
    }
    __syncthreads();
    #pragma unroll
    for (int p = 0; p < 4; p++) {
        int n = p * 16 + (t >> 4);
        int k4 = (t & 15) * 4;
        size_t o = (size_t)z * D * D + (size_t)(n0 + n) * D + k0 + k4;
        *(uint2*)&g_WhiT[o]  = *(const uint2*)&th[n][k4];
        *(uint2*)&g_WmidT[o] = *(const uint2*)&tm[n][k4];
    }
}

// ===================== HMMA GEMM mainloop: cp.async pipelined, 32-k stages =============
#define PLDA 80
#define PTILE (128*PLDA)       // 10240
#define STG   (4*PTILE)        // 40960
#define GEMM_SMEM (2*STG)      // 81920

#define HG_PREFETCH(sidx, buf) do { \
    _Pragma("unroll") \
    for (int p = 0; p < 2; p++) { \
        int idx = p * 256 + tid; \
        int row = idx >> 2, cg = idx & 3; \
        uint32_t so = (buf) + row * PLDA + cg * 16; \
        size_t gofs = (size_t)row * D + (sidx) * 32; \
        CP16(so,             (const char*)(Ah + gofs) + cg * 16); \
        CP16(so +   PTILE,   (const char*)(Am + gofs) + cg * 16); \
        CP16(so + 2*PTILE,   (const char*)(Bh + gofs) + cg * 16); \
        CP16(so + 3*PTILE,   (const char*)(Bm + gofs) + cg * 16); \
    } \
    CP_COMMIT(); \
} while (0)

__device__ __forceinline__ void hgemm_main(
    const __nv_bfloat16* __restrict__ Ah, const __nv_bfloat16* __restrict__ Am,
    const __nv_bfloat16* __restrict__ Bh, const __nv_bfloat16* __restrict__ Bm,
    char* smem, float acc[4][4][4])
{
    const int tid = threadIdx.x, lane = tid & 31, wid = tid >> 5;
    const int wm = wid >> 2, wn = wid & 3;
    const uint32_t sb = smem_u32(smem);

    HG_PREFETCH(0, sb);

    const uint32_t a_row = (uint32_t)(wm * 64 + (lane & 15)) * PLDA + (lane >> 4) * 16;
    const uint32_t b_row = (uint32_t)(wn * 32 + (lane & 7)) * PLDA + ((lane >> 3) & 1) * 16;

    for (int s = 0; s < 32; s++) {
        CP_WAIT0();
        __syncthreads();
        if (s + 1 < 32) HG_PREFETCH(s + 1, sb + (uint32_t)(((s + 1) & 1) * STG));

        const uint32_t base = sb + (uint32_t)((s & 1) * STG);
        #pragma unroll
        for (int ks = 0; ks < 2; ks++) {
            uint32_t ah[4][4], am[4][4], bh[4][2], bm[4][2];
            #pragma unroll
            for (int mt = 0; mt < 4; mt++) {
                uint32_t ra = base + a_row + mt * (16 * PLDA) + ks * 32;
                LDSM4(ah[mt], ra);
                LDSM4(am[mt], ra + PTILE);
            }
            #pragma unroll
            for (int nt = 0; nt < 4; nt++) {
                uint32_t rb = base + 2 * PTILE + b_row + nt * (8 * PLDA) + ks * 32;
                LDSM2(bh[nt], rb);
                LDSM2(bm[nt], rb + PTILE);
            }
            #pragma unroll
            for (int mt = 0; mt < 4; mt++)
                #pragma unroll
                for (int nt = 0; nt < 4; nt++) {
                    MMA16816(acc[mt][nt], ah[mt], bh[nt]);
                    MMA16816(acc[mt][nt], ah[mt], bm[nt]);
                    MMA16816(acc[mt][nt], am[mt], bh[nt]);
                }
        }
    }
    __syncthreads();
}

// ===================== QKV GEMM: epilogue writes split bf16 head-major =====================
__global__ __launch_bounds__(256) void qkv_mm(
    const float* __restrict__ bq, const float* __restrict__ bk, const float* __restrict__ bv)
{
    extern __shared__ char smem[];
    const int z = blockIdx.z, m0 = blockIdx.y * 128, n0 = blockIdx.x * 128;
    float acc[4][4][4] = {};
    hgemm_main(g_Xhi + ((size_t)z * MROWS + m0) * D, g_Xmid + ((size_t)z * MROWS + m0) * D,
               g_WhiT + ((size_t)z * D + n0) * D,    g_WmidT + ((size_t)z * D + n0) * D,
               smem, acc);

    const float* bias = (z == 0) ? bq : (z == 1) ? bk : bv;
    __nv_bfloat16* outh = (z == 0) ? g_Qh : (z == 1) ? g_Kh : g_Vh;
    __nv_bfloat16* outm = (z == 0) ? g_Qm : (z == 1) ? g_Km : g_Vm;
    const int tid = threadIdx.x, lane = tid & 31, wid = tid >> 5;
    const int wm = wid >> 2, wn = wid & 3;
    const int g2 = lane >> 2, t4 = lane & 3;

    #pragma unroll
    for (int nt = 0; nt < 4; nt++) {
        const int c = n0 + wn * 32 + nt * 8 + 2 * t4;
        const float b0v = __ldg(&bias[c]), b1v = __ldg(&bias[c + 1]);
        const int h = c >> 6, d = c & 63;
        #pragma unroll
        for (int mt = 0; mt < 4; mt++) {
            int r0 = m0 + wm * 64 + mt * 16 + g2;
            int b = r0 >> 11, s = r0 & (S - 1);
            size_t base = ((size_t)(b * H + h) * S + s) * DK + d;
            #pragma unroll
            for (int hp = 0; hp < 2; hp++) {
                float v0 = acc[mt][nt][2*hp + 0] + b0v;
                float v1 = acc[mt][nt][2*hp + 1] + b1v;
                __nv_bfloat16 h0 = __float2bfloat16(v0), h1 = __float2bfloat16(v1);
                size_t o = base + (size_t)hp * 8 * DK;
                *(__nv_bfloat162*)(outh + o) = __halves2bfloat162(h0, h1);
                *(__nv_bfloat162*)(outm + o) = __halves2bfloat162(
                    __float2bfloat16(v0 - __bfloat162float(h0)),
                    __float2bfloat16(v1 - __bfloat162float(h1)));
            }
        }
    }
}

// ===================== O-proj GEMM (row-major epilogue) =====================
__global__ __launch_bounds__(256) void o_mm(const float* __restrict__ bo, float* __restrict__ out)
{
    extern __shared__ char smem[];
    const int m0 = blockIdx.y * 128, n0 = blockIdx.x * 128;
    float acc[4][4][4] = {};
    hgemm_main(g_ctx_hi + (size_t)m0 * D, g_ctx_mid + (size_t)m0 * D,
               g_WhiT + ((size_t)3 * D + n0) * D, g_WmidT + ((size_t)3 * D + n0) * D,
               smem, acc);

    const int tid = threadIdx.x, lane = tid & 31, wid = tid >> 5;
    const int wm = wid >> 2, wn = wid & 3;
    const int g2 = lane >> 2, t4 = lane & 3;

    #pragma unroll
    for (int nt = 0; nt < 4; nt++) {
        const int c = n0 + wn * 32 + nt * 8 + 2 * t4;
        const float b0v = __ldg(&bo[c]), b1v = __ldg(&bo[c + 1]);
        #pragma unroll
        for (int mt = 0; mt < 4; mt++) {
            int r0 = m0 + wm * 64 + mt * 16 + g2;
            float* p0 = out + (size_t)r0 * D + c;
            *(float2*)p0 = make_float2(acc[mt][nt][0] + b0v, acc[mt][nt][1] + b1v);
            float* p1 = p0 + 8 * D;
            *(float2*)p1 = make_float2(acc[mt][nt][2] + b0v, acc[mt][nt][3] + b1v);
        }
    }
}

// ===================== attention kernel 1: row sums, 64-row q-tiles (measured best) =====
#define LDA 144
#define ST_QH 0
#define ST_QM 9216
#define ST_K0 18432
#define ST_K1 36864
#define ST_SMEM 55296

__global__ __launch_bounds__(256) void stats_mm()
{
    extern __shared__ char smem[];
    const uint32_t sb = smem_u32(smem);
    const int tid = threadIdx.x, lane = tid & 31, wid = tid >> 5;
    const int wm = wid >> 2, wn = wid & 3;
    const int g2 = lane >> 2, t4 = lane & 3;
    const int q0 = blockIdx.x * 64, bh = blockIdx.y;

    const __nv_bfloat16* Qh = g_Qh + ((size_t)bh * S + q0) * DK;
    const __nv_bfloat16* Qm = g_Qm + ((size_t)bh * S + q0) * DK;
    const __nv_bfloat16* Kh = g_Kh + (size_t)bh * S * DK;
    const __nv_bfloat16* Km = g_Km + (size_t)bh * S * DK;

    #pragma unroll
    for (int p = 0; p < 4; p++) {
        int idx = p * 256 + tid;
        int row = idx >> 4, cg = idx & 15;
        size_t g = (size_t)row * DK + cg * 4;
        int so = row * LDA + cg * 8;
        *(uint2*)(smem + ST_QH + so) = *(const uint2*)(Qh + g);
        *(uint2*)(smem + ST_QM + so) = *(const uint2*)(Qm + g);
    }

    #pragma unroll
    for (int p = 0; p < 2; p++) {
        int idx = p * 256 + tid;
        int row = idx >> 3, cg = idx & 7;
        uint32_t so = sb + ST_K0 + row * LDA + cg * 16;
        CP16(so,        (const char*)(Kh + (size_t)row * DK) + cg * 16);
        CP16(so + 9216, (const char*)(Km + (size_t)row * DK) + cg * 16);
    }
    CP_COMMIT();

    const uint32_t aQ = sb + ST_QH + (uint32_t)(wm * 32 + (lane & 15)) * LDA + (lane >> 4) * 16;
    const uint32_t bKoff = (uint32_t)(wn * 16 + (lane & 7)) * LDA + ((lane >> 3) & 1) * 16;

    float sums[2][2] = {};

    for (int c = 0; c < 32; c++) {
        CP_WAIT0();
        __syncthreads();
        if (c + 1 < 32) {
            const int kt = (c + 1) * 64;
            const uint32_t kb = sb + (((c + 1) & 1) ? ST_K1 : ST_K0);
            #pragma unroll
            for (int p = 0; p < 2; p++) {
                int idx = p * 256 + tid;
                int row = idx >> 3, cg = idx & 7;
                uint32_t so = kb + row * LDA + cg * 16;
                CP16(so,        (const char*)(Kh + (size_t)(kt + row) * DK) + cg * 16);
                CP16(so + 9216, (const char*)(Km + (size_t)(kt + row) * DK) + cg * 16);
            }
            CP_COMMIT();
        }

        const uint32_t bK = sb + ((c & 1) ? ST_K1 : ST_K0) + bKoff;
        float sacc[2][2][4] = {};
        #pragma unroll
        for (int ks = 0; ks < 4; ks++) {
            uint32_t qh[2][4], qm[2][4];
            #pragma unroll
            for (int mt = 0; mt < 2; mt++) {
                uint32_t ra = aQ + mt * (16 * LDA) + ks * 32;
                LDSM4(qh[mt], ra);
                LDSM4(qm[mt], ra + (ST_QM - ST_QH));
            }
            #pragma unroll
            for (int nt = 0; nt < 2; nt++) {
                uint32_t rb = bK + nt * (8 * LDA) + ks * 32;
                uint32_t kbh[2], kbm[2];
                LDSM2(kbh, rb);
                LDSM2(kbm, rb + 9216);
                #pragma unroll
                for (int mt = 0; mt < 2; mt++) {
                    MMA16816(sacc[mt][nt], qh[mt], kbh);
                    MMA16816(sacc[mt][nt], qh[mt], kbm);
                    MMA16816(sacc[mt][nt], qm[mt], kbh);
                }
            }
        }
        #pragma unroll
        for (int mt = 0; mt < 2; mt++)
            #pragma unroll
            for (int nt = 0; nt < 2; nt++) {
                sums[mt][0] += fexp(sacc[mt][nt][0] * 0.125f) + fexp(sacc[mt][nt][1] * 0.125f);
                sums[mt][1] += fexp(sacc[mt][nt][2] * 0.125f) + fexp(sacc[mt][nt][3] * 0.125f);
            }
    }

    #pragma unroll
    for (int mt = 0; mt < 2; mt++)
        #pragma unroll
        for (int hp = 0; hp < 2; hp++) {
            sums[mt][hp] += __shfl_xor_sync(0xffffffffu, sums[mt][hp], 1);
            sums[mt][hp] += __shfl_xor_sync(0xffffffffu, sums[mt][hp], 2);
        }
    __syncthreads();
    float* sbuf = (float*)(smem + ST_K0);
    if (t4 == 0) {
        #pragma unroll
        for (int mt = 0; mt < 2; mt++)
            #pragma unroll
            for (int hp = 0; hp < 2; hp++)
                sbuf[wn * 64 + wm * 32 + mt * 16 + g2 + 8 * hp] = sums[mt][hp];
    }
    __syncthreads();
    if (tid < 64) {
        float s = sbuf[tid] + sbuf[64 + tid] + sbuf[128 + tid] + sbuf[192 + tid];
        g_rinv[(size_t)bh * S + q0 + tid] = 1.0f / s;
    }
}

// ===================== attention kernel 2: pipelined softmax-apply + PV ================
// grid (16 m-tiles, 32 bh), block 256. Warp layout 4x2. 32-row K/V stages, cp.async 2-buf.
// smem: QH@0 (18432), QM@18432, KV0@36864 (Kh+0,Km+4608,Vh+9216,Vm+13824; 18432),
//       KV1@55296, PH@73728 (128x80=10240), PM@83968, RINV@94208 -> 94720
#define FB_QH   0
#define FB_QM   18432
#define FB_KV0  36864
#define FB_KV1  55296
#define FB_PH   73728
#define FB_PM   83968
#define FB_RINV 94208
#define FB_SMEM 94720

#define FB_PREFETCH(kt_, buf) do { \
    int row = tid >> 3, cg = tid & 7; \
    size_t g = (size_t)((kt_) + row) * DK; \
    uint32_t so = (buf) + row * LDA + cg * 16; \
    CP16(so,         (const char*)(Kh + g) + cg * 16); \
    CP16(so + 4608,  (const char*)(Km + g) + cg * 16); \
    CP16(so + 9216,  (const char*)(Vh + g) + cg * 16); \
    CP16(so + 13824, (const char*)(Vm + g) + cg * 16); \
    CP_COMMIT(); \
} while (0)

__global__ __launch_bounds__(256) void fused_pv(float* __restrict__ attn)
{
    extern __shared__ char smem[];
    const uint32_t sb = smem_u32(smem);
    float* sRinv = (float*)(smem + FB_RINV);

    const int tid = threadIdx.x, lane = tid & 31, wid = tid >> 5;
    const int wm = wid >> 1, wn = wid & 1;
    const int g2 = lane >> 2, t4 = lane & 3;
    const int q0 = blockIdx.x * 128, bh = blockIdx.y;
    const int b = bh >> 4, h = bh & 15;

    const __nv_bfloat16* Qh = g_Qh + ((size_t)bh * S + q0) * DK;
    const __nv_bfloat16* Qm = g_Qm + ((size_t)bh * S + q0) * DK;
    const __nv_bfloat16* Kh = g_Kh + (size_t)bh * S * DK;
    const __nv_bfloat16* Km = g_Km + (size_t)bh * S * DK;
    const __nv_bfloat16* Vh = g_Vh + (size_t)bh * S * DK;
    const __nv_bfloat16* Vm = g_Vm + (size_t)bh * S * DK;
    float* attnBase = attn + ((size_t)bh * S + q0) * S;

    FB_PREFETCH(0, sb + FB_KV0);

    #pragma unroll
    for (int p = 0; p < 8; p++) {
        int idx = p * 256 + tid;
        int row = idx >> 4, cg = idx & 15;
        size_t g = (size_t)row * DK + cg * 4;
        int so = row * LDA + cg * 8;
        *(uint2*)(smem + FB_QH + so) = *(const uint2*)(Qh + g);
        *(uint2*)(smem + FB_QM + so) = *(const uint2*)(Qm + g);
    }
    if (tid < 128) sRinv[tid] = g_rinv[(size_t)bh * S + q0 + tid];

    const uint32_t aQ = sb + FB_QH + (uint32_t)(wm * 32 + (lane & 15)) * LDA + (lane >> 4) * 16;
    const uint32_t bKoff = (uint32_t)(wn * 16 + (lane & 7)) * LDA + ((lane >> 3) & 1) * 16;
    const uint32_t aP = sb + FB_PH + (uint32_t)(wm * 32 + (lane & 15)) * PLDA + (lane >> 4) * 16;
    const uint32_t bVoff = 9216u + (uint32_t)((lane & 7) + ((lane >> 3) & 1) * 8) * LDA + wn * 64;

    float pacc[2][4][4] = {};

    for (int c = 0; c < 64; c++) {
        CP_WAIT0();
        __syncthreads();
        if (c + 1 < 64)
            FB_PREFETCH((c + 1) * 32, sb + (((c + 1) & 1) ? FB_KV1 : FB_KV0));

        const uint32_t kvb = sb + ((c & 1) ? FB_KV1 : FB_KV0);
        const int kt = c * 32;

        // scores: warp = 32 rows x 16 k-cols (wn half of the 32-key stage)
        float sacc[2][2][4] = {};
        #pragma unroll
        for (int ks = 0; ks < 4; ks++) {
            uint32_t qh[2][4], qm[2][4];
            #pragma unroll
            for (int mt = 0; mt < 2; mt++) {
                uint32_t ra = aQ + mt * (16 * LDA) + ks * 32;
                LDSM4(qh[mt], ra);
                LDSM4(qm[mt], ra + (FB_QM - FB_QH));
            }
            #pragma unroll
            for (int nt = 0; nt < 2; nt++) {
                uint32_t rb = kvb + bKoff + nt * (8 * LDA) + ks * 32;
                uint32_t kbh[2], kbm[2];
                LDSM2(kbh, rb);
                LDSM2(kbm, rb + 4608);
                #pragma unroll
                for (int mt = 0; mt < 2; mt++) {
                    MMA16816(sacc[mt][nt], qh[mt], kbh);
                    MMA16816(sacc[mt][nt], qh[mt], kbm);
                    MMA16816(sacc[mt][nt], qm[mt], kbh);
                }
            }
        }

        // softmax-apply: write attn + split-bf16 P (stride 80)
        #pragma unroll
        for (int mt = 0; mt < 2; mt++) {
            int rl0 = wm * 32 + mt * 16 + g2;
            float iv0 = sRinv[rl0], iv1 = sRinv[rl0 + 8];
            #pragma unroll
            for (int nt = 0; nt < 2; nt++) {
                int cl = wn * 16 + nt * 8 + t4 * 2;
                float p00 = fexp(sacc[mt][nt][0] * 0.125f) * iv0;
                float p01 = fexp(sacc[mt][nt][1] * 0.125f) * iv0;
                float p10 = fexp(sacc[mt][nt][2] * 0.125f) * iv1;
                float p11 = fexp(sacc[mt][nt][3] * 0.125f) * iv1;
                *(float2*)(attnBase + (size_t)rl0 * S + kt + cl)       = make_float2(p00, p01);
                *(float2*)(attnBase + (size_t)(rl0 + 8) * S + kt + cl) = make_float2(p10, p11);
                __nv_bfloat16 h00 = __float2bfloat16(p00), h01 = __float2bfloat16(p01);
                __nv_bfloat16 h10 = __float2bfloat16(p10), h11 = __float2bfloat16(p11);
                *(__nv_bfloat162*)(smem + FB_PH + rl0 * PLDA + cl * 2) = __halves2bfloat162(h00, h01);
                *(__nv_bfloat162*)(smem + FB_PH + (rl0 + 8) * PLDA + cl * 2) = __halves2bfloat162(h10, h11);
                *(__nv_bfloat162*)(smem + FB_PM + rl0 * PLDA + cl * 2) = __halves2bfloat162(
                    __float2bfloat16(p00 - __bfloat162float(h00)),
                    __float2bfloat16(p01 - __bfloat162float(h01)));
                *(__nv_bfloat162*)(smem + FB_PM + (rl0 + 8) * PLDA + cl * 2) = __halves2bfloat162(
                    __float2bfloat16(p10 - __bfloat162float(h10)),
                    __float2bfloat16(p11 - __bfloat162float(h11)));
            }
        }
        __syncthreads();

        // PV MMA over the 32-key stage: ks in {0,1}
        #pragma unroll
        for (int ks = 0; ks < 2; ks++) {
            uint32_t ph[2][4], pm[2][4];
            #pragma unroll
            for (int mt = 0; mt < 2; mt++) {
                uint32_t ra = aP + mt * (16 * PLDA) + ks * 32;
                LDSM4(ph[mt], ra);
                LDSM4(pm[mt], ra + (FB_PM - FB_PH));
            }
            #pragma unroll
            for (int nt = 0; nt < 4; nt++) {
                uint32_t rv = kvb + bVoff + ks * (16 * LDA) + nt * 16;
                uint32_t vh2[2], vm2[2];
                LDSM2T(vh2, rv);
                LDSM2T(vm2, rv + 4608);
                #pragma unroll
                for (int mt = 0; mt < 2; mt++) {
                    MMA16816(pacc[mt][nt], ph[mt], vh2);
                    MMA16816(pacc[mt][nt], ph[mt], vm2);
                    MMA16816(pacc[mt][nt], pm[mt], vh2);
                }
            }
        }
    }

    __syncthreads();
    // ctx epilogue: split-bf16
    #pragma unroll
    for (int nt = 0; nt < 4; nt++) {
        const int c = h * DK + wn * 32 + nt * 8 + 2 * t4;
        #pragma unroll
        for (int mt = 0; mt < 2; mt++) {
            int r0 = q0 + wm * 32 + mt * 16 + g2;
            #pragma unroll
            for (int hp = 0; hp < 2; hp++) {
                float v0 = pacc[mt][nt][2*hp + 0], v1 = pacc[mt][nt][2*hp + 1];
                __nv_bfloat16 h0 = __float2bfloat16(v0), h1 = __float2bfloat16(v1);
                size_t o = ((size_t)(b * S) + r0 + 8 * hp) * D + c;
                *(__nv_bfloat162*)(g_ctx_hi + o) = __halves2bfloat162(h0, h1);
                *(__nv_bfloat162*)(g_ctx_mid + o) = __halves2bfloat162(
                    __float2bfloat16(v0 - __bfloat162float(h0)),
                    __float2bfloat16(v1 - __bfloat162float(h1)));
            }
        }
    }
}

// ===================== launch =====================
extern "C" void kernel_launch(void* const* d_in, const int* in_sizes, int n_in,
                              void* d_out, int out_size)
{
    const float* query = (const float*)d_in[0];
    const float* key   = (const float*)d_in[1];
    const float* value = (const float*)d_in[2];
    const float* Wq = (const float*)d_in[3];
    const float* bq = (const float*)d_in[4];
    const float* Wk = (const float*)d_in[5];
    const float* bk = (const float*)d_in[6];
    const float* Wv = (const float*)d_in[7];
    const float* bv = (const float*)d_in[8];
    const float* Wo = (const float*)d_in[9];
    const float* bo = (const float*)d_in[10];

    float* out  = (float*)d_out;
    float* attn = out + (size_t)MROWS * D;

    cudaFuncSetAttribute(qkv_mm, cudaFuncAttributeMaxDynamicSharedMemorySize, GEMM_SMEM);
    cudaFuncSetAttribute(o_mm, cudaFuncAttributeMaxDynamicSharedMemorySize, GEMM_SMEM);
    cudaFuncSetAttribute(stats_mm, cudaFuncAttributeMaxDynamicSharedMemorySize, ST_SMEM);
    cudaFuncSetAttribute(fused_pv, cudaFuncAttributeMaxDynamicSharedMemorySize, FB_SMEM);

    conv_acts<<<3 * MROWS * D / 4 / 256, 256>>>(query, key, value);
    conv_W<<<dim3(16, 16, 4), 256>>>(Wq, Wk, Wv, Wo);
    qkv_mm<<<dim3(8, 32, 3), 256, GEMM_SMEM>>>(bq, bk, bv);
    stats_mm<<<dim3(32, 32), 256, ST_SMEM>>>();
    fused_pv<<<dim3(16, 32), 256, FB_SMEM>>>(attn);
    o_mm<<<dim3(8, 32), 256, GEMM_SMEM>>>(bo, out);
}